// round 2
// baseline (speedup 1.0000x reference)
#include <cuda_runtime.h>
#include <cstdint>
#include <math_constants.h>

// Problem constants (fixed by the reference):
//   B=64, I=1024, O=1024, et in {0,1,2}
//   tnorm (op==0): val = (et==2 ? 1-x : x) + (et==0 ? +10 : 0), reduce = min
//   tconorm:       val = (et==2 ? 1-x : x) + (et==0 ? -10 : 0), reduce = max
// Sign trick: s = tnorm ? +1 : -1.  w = s*v = (et==2 ? s - s*x : s*x) + (et==0 ? 10 : 0)
//   answer = s * min(w)   (since max(v) = -min(-v), and s*offset = +10 in both cases)

#define B_DIM 64
#define I_DIM 1024
#define O_DIM 1024
#define THREADS 512
#define WARPS 16
#define ROWS_PER_BLOCK 8        // 2 warps cooperate per output row
#define GROUPS_PER_B (O_DIM / ROWS_PER_BLOCK)   // 128

__global__ void __launch_bounds__(THREADS, 3)
ffcl_kernel(const float* __restrict__ x,
            const int4* __restrict__ et4,       // edge_type_idx viewed as int4
            const int* __restrict__ op_idx,
            float* __restrict__ out)
{
    __shared__ float xs[I_DIM];
    __shared__ float partial[WARPS];

    const int b  = blockIdx.x >> 7;             // / GROUPS_PER_B
    const int og = blockIdx.x & (GROUPS_PER_B - 1);

    // Stage x[b, :] into shared (4 KB)
    {
        const float4* xrow = reinterpret_cast<const float4*>(x + (size_t)b * I_DIM);
        float4* xs4w = reinterpret_cast<float4*>(xs);
        #pragma unroll
        for (int i = threadIdx.x; i < I_DIM / 4; i += THREADS)
            xs4w[i] = xrow[i];
    }
    __syncthreads();

    const int warp = threadIdx.x >> 5;
    const int lane = threadIdx.x & 31;
    const int r    = warp >> 1;                 // row within block: 0..7
    const int half = warp & 1;                  // which half of I this warp covers
    const int o    = og * ROWS_PER_BLOCK + r;

    const bool  tnorm = (op_idx[o] == 0);
    const float s     = tnorm ? 1.0f : -1.0f;

    // et row for (b, o): 1024 ints = 256 int4; this warp takes 128 of them.
    const int4* row = et4 + ((size_t)(b * O_DIM + o) * (I_DIM / 4)) + half * 128;
    const float4* xs4 = reinterpret_cast<const float4*>(xs) + half * 128;

    // Front-batched loads: 4 independent LDG.128 per lane (streaming).
    int4 e[4];
    #pragma unroll
    for (int j = 0; j < 4; ++j)
        e[j] = __ldcs(row + j * 32 + lane);

    float red = CUDART_INF_F;

    #pragma unroll
    for (int j = 0; j < 4; ++j) {
        const float4 xv = xs4[j * 32 + lane];
        float t0 = s * xv.x, t1 = s * xv.y, t2 = s * xv.z, t3 = s * xv.w;
        float v0 = (e[j].x == 2) ? (s - t0) : t0;
        float v1 = (e[j].y == 2) ? (s - t1) : t1;
        float v2 = (e[j].z == 2) ? (s - t2) : t2;
        float v3 = (e[j].w == 2) ? (s - t3) : t3;
        if (e[j].x == 0) v0 += 10.0f;
        if (e[j].y == 0) v1 += 10.0f;
        if (e[j].z == 0) v2 += 10.0f;
        if (e[j].w == 0) v3 += 10.0f;
        red = fminf(red, fminf(fminf(v0, v1), fminf(v2, v3)));
    }

    // Warp butterfly min
    #pragma unroll
    for (int sh = 16; sh > 0; sh >>= 1)
        red = fminf(red, __shfl_xor_sync(0xffffffffu, red, sh));

    if (lane == 0) partial[warp] = red;
    __syncthreads();

    if (half == 0 && lane == 0)
        out[(size_t)b * O_DIM + o] = s * fminf(partial[warp], partial[warp + 1]);
}

extern "C" void kernel_launch(void* const* d_in, const int* in_sizes, int n_in,
                              void* d_out, int out_size)
{
    (void)in_sizes; (void)n_in; (void)out_size;
    const float* x      = (const float*)d_in[0];
    const int4*  et4    = (const int4*)d_in[1];
    const int*   op_idx = (const int*)d_in[2];
    float*       out    = (float*)d_out;

    const int blocks = B_DIM * GROUPS_PER_B;   // 64 * 128 = 8192
    ffcl_kernel<<<blocks, THREADS>>>(x, et4, op_idx, out);
}

// round 3
// speedup vs baseline: 1.0307x; 1.0307x over previous
#include <cuda_runtime.h>
#include <cstdint>
#include <math_constants.h>

// Problem constants (fixed by the reference):
//   B=64, I=1024, O=1024, et in {0,1,2}
//   tnorm (op==0): val = (et==2 ? 1-x : x) + (et==0 ? +10 : 0), reduce = min
//   tconorm:       val = (et==2 ? 1-x : x) + (et==0 ? -10 : 0), reduce = max
// Sign trick: s = tnorm ? +1 : -1.  w = s*v = (et==2 ? s - s*x : s*x) + (et==0 ? 10 : 0)
//   answer = s * min(w)   (exact: multiply by +/-1; s*offset = +10 in both cases)

#define B_DIM 64
#define I_DIM 1024
#define O_DIM 1024
#define THREADS 256
#define WARPS_PB 8
#define ROWS_PER_WARP 4
#define ROWS_PER_BLOCK (WARPS_PB * ROWS_PER_WARP)       // 32
#define GROUPS_PER_B (O_DIM / ROWS_PER_BLOCK)           // 32

// Reduce one half-batch: 4 int4 of et + matching 4 float4 of x (from smem).
// Returns min over the 16 elements of w = s*v.
static __device__ __forceinline__
float half_row_min(const int4* __restrict__ e, const float4* __restrict__ xs4,
                   int lane, float s)
{
    float red = CUDART_INF_F;
    #pragma unroll
    for (int j = 0; j < 4; ++j) {
        const float4 xv = xs4[j * 32 + lane];
        float t0 = s * xv.x, t1 = s * xv.y, t2 = s * xv.z, t3 = s * xv.w;
        float v0 = (e[j].x == 2) ? (s - t0) : t0;
        float v1 = (e[j].y == 2) ? (s - t1) : t1;
        float v2 = (e[j].z == 2) ? (s - t2) : t2;
        float v3 = (e[j].w == 2) ? (s - t3) : t3;
        if (e[j].x == 0) v0 += 10.0f;
        if (e[j].y == 0) v1 += 10.0f;
        if (e[j].z == 0) v2 += 10.0f;
        if (e[j].w == 0) v3 += 10.0f;
        red = fminf(red, fminf(fminf(v0, v1), fminf(v2, v3)));
    }
    return red;
}

__global__ void __launch_bounds__(THREADS, 4)
ffcl_kernel(const float* __restrict__ x,
            const int4* __restrict__ et4,       // edge_type_idx viewed as int4
            const int* __restrict__ op_idx,
            float* __restrict__ out)
{
    __shared__ float xs[I_DIM];

    const int b = blockIdx.x >> 5;              // / GROUPS_PER_B
    const int g = blockIdx.x & (GROUPS_PER_B - 1);

    // Stage x[b, :] into shared (4 KB): exactly one float4 per thread.
    {
        const float4* xrow = reinterpret_cast<const float4*>(x + (size_t)b * I_DIM);
        reinterpret_cast<float4*>(xs)[threadIdx.x] = xrow[threadIdx.x];
    }
    __syncthreads();

    const int warp = threadIdx.x >> 5;
    const int lane = threadIdx.x & 31;
    const int o0   = g * ROWS_PER_BLOCK + warp * ROWS_PER_WARP;

    // Preload signs for this warp's 4 rows (tiny, L1/L2-cached).
    float sgn[ROWS_PER_WARP];
    #pragma unroll
    for (int r = 0; r < ROWS_PER_WARP; ++r)
        sgn[r] = (op_idx[o0 + r] == 0) ? 1.0f : -1.0f;

    const int4*   base = et4 + (size_t)(b * O_DIM + o0) * (I_DIM / 4);
    const float4* xs4  = reinterpret_cast<const float4*>(xs);

    // Software pipeline: A holds the half-batch being computed, the other
    // half-batch's loads are always already in flight.
    int4 A[4], Bv[4];

    // Prologue: first half of row 0.
    #pragma unroll
    for (int j = 0; j < 4; ++j)
        A[j] = __ldcs(base + j * 32 + lane);

    #pragma unroll
    for (int r = 0; r < ROWS_PER_WARP; ++r) {
        const int4* rowp = base + r * (I_DIM / 4);
        const float s = sgn[r];

        // Issue second half of row r, then compute first half.
        #pragma unroll
        for (int j = 0; j < 4; ++j)
            Bv[j] = __ldcs(rowp + 128 + j * 32 + lane);

        float red = half_row_min(A, xs4, lane, s);

        // Issue first half of row r+1 (overlaps B compute + reduction + store).
        if (r + 1 < ROWS_PER_WARP) {
            #pragma unroll
            for (int j = 0; j < 4; ++j)
                A[j] = __ldcs(rowp + 256 + j * 32 + lane);
        }

        red = fminf(red, half_row_min(Bv, xs4 + 128, lane, s));

        // Warp butterfly min (overlapped with next row's in-flight loads).
        #pragma unroll
        for (int sh = 16; sh > 0; sh >>= 1)
            red = fminf(red, __shfl_xor_sync(0xffffffffu, red, sh));

        if (lane == 0)
            out[(size_t)b * O_DIM + o0 + r] = s * red;
    }
}

extern "C" void kernel_launch(void* const* d_in, const int* in_sizes, int n_in,
                              void* d_out, int out_size)
{
    (void)in_sizes; (void)n_in; (void)out_size;
    const float* x      = (const float*)d_in[0];
    const int4*  et4    = (const int4*)d_in[1];
    const int*   op_idx = (const int*)d_in[2];
    float*       out    = (float*)d_out;

    const int blocks = B_DIM * GROUPS_PER_B;   // 64 * 32 = 2048
    ffcl_kernel<<<blocks, THREADS>>>(x, et4, op_idx, out);
}

// round 4
// speedup vs baseline: 1.0468x; 1.0156x over previous
#include <cuda_runtime.h>
#include <cstdint>
#include <math_constants.h>

// Problem constants (fixed by the reference):
//   B=64, I=1024, O=1024, et in {0,1,2}
//   tnorm (op==0): val = (et==2 ? 1-x : x) + (et==0 ? +10 : 0), reduce = min
//   tconorm:       val = (et==2 ? 1-x : x) + (et==0 ? -10 : 0), reduce = max
// Sign trick: s = tnorm ? +1 : -1.  w = s*v = (et==2 ? s - s*x : s*x) + (et==0 ? 10 : 0)
//   answer = s * min(w)   (exact: multiply by +/-1; s*offset = +10 in both cases)

#define B_DIM 64
#define I_DIM 1024
#define O_DIM 1024
#define THREADS 256
#define WARPS_PB 8
#define ROWS_PER_WARP 2
#define ROWS_PER_BLOCK (WARPS_PB * ROWS_PER_WARP)       // 16
#define GROUPS_PER_B (O_DIM / ROWS_PER_BLOCK)           // 64

// Reduce one half-batch: 4 int4 of et + matching 4 float4 of x (from smem).
// Returns min over the 16 elements of w = s*v.
static __device__ __forceinline__
float half_row_min(const int4* __restrict__ e, const float4* __restrict__ xs4,
                   int lane, float s)
{
    float red = CUDART_INF_F;
    #pragma unroll
    for (int j = 0; j < 4; ++j) {
        const float4 xv = xs4[j * 32 + lane];
        float t0 = s * xv.x, t1 = s * xv.y, t2 = s * xv.z, t3 = s * xv.w;
        float v0 = (e[j].x == 2) ? (s - t0) : t0;
        float v1 = (e[j].y == 2) ? (s - t1) : t1;
        float v2 = (e[j].z == 2) ? (s - t2) : t2;
        float v3 = (e[j].w == 2) ? (s - t3) : t3;
        if (e[j].x == 0) v0 += 10.0f;
        if (e[j].y == 0) v1 += 10.0f;
        if (e[j].z == 0) v2 += 10.0f;
        if (e[j].w == 0) v3 += 10.0f;
        red = fminf(red, fminf(fminf(v0, v1), fminf(v2, v3)));
    }
    return red;
}

__global__ void __launch_bounds__(THREADS, 4)
ffcl_kernel(const float* __restrict__ x,
            const int4* __restrict__ et4,       // edge_type_idx viewed as int4
            const int* __restrict__ op_idx,
            float* __restrict__ out)
{
    __shared__ float xs[I_DIM];

    const int b = blockIdx.x >> 6;              // / GROUPS_PER_B
    const int g = blockIdx.x & (GROUPS_PER_B - 1);

    // Stage x[b, :] into shared (4 KB): exactly one float4 per thread.
    {
        const float4* xrow = reinterpret_cast<const float4*>(x + (size_t)b * I_DIM);
        reinterpret_cast<float4*>(xs)[threadIdx.x] = xrow[threadIdx.x];
    }
    __syncthreads();

    const int warp = threadIdx.x >> 5;
    const int lane = threadIdx.x & 31;
    const int o0   = g * ROWS_PER_BLOCK + warp * ROWS_PER_WARP;

    // Signs for this warp's rows (tiny, cached).
    float sgn[ROWS_PER_WARP];
    #pragma unroll
    for (int r = 0; r < ROWS_PER_WARP; ++r)
        sgn[r] = (op_idx[o0 + r] == 0) ? 1.0f : -1.0f;

    const int4*   base = et4 + (size_t)(b * O_DIM + o0) * (I_DIM / 4);
    const float4* xs4  = reinterpret_cast<const float4*>(xs);

    // Software pipeline: A holds the half-batch being computed, the other
    // half-batch's loads are always already in flight.
    int4 A[4], Bv[4];

    // Prologue: first half of row 0.
    #pragma unroll
    for (int j = 0; j < 4; ++j)
        A[j] = __ldcs(base + j * 32 + lane);

    #pragma unroll
    for (int r = 0; r < ROWS_PER_WARP; ++r) {
        const int4* rowp = base + r * (I_DIM / 4);
        const float s = sgn[r];

        // Issue second half of row r, then compute first half.
        #pragma unroll
        for (int j = 0; j < 4; ++j)
            Bv[j] = __ldcs(rowp + 128 + j * 32 + lane);

        float red = half_row_min(A, xs4, lane, s);

        // Issue first half of row r+1 (overlaps B compute + reduction + store).
        if (r + 1 < ROWS_PER_WARP) {
            #pragma unroll
            for (int j = 0; j < 4; ++j)
                A[j] = __ldcs(rowp + 256 + j * 32 + lane);
        }

        red = fminf(red, half_row_min(Bv, xs4 + 128, lane, s));

        // Warp butterfly min (overlapped with next row's in-flight loads).
        #pragma unroll
        for (int sh = 16; sh > 0; sh >>= 1)
            red = fminf(red, __shfl_xor_sync(0xffffffffu, red, sh));

        if (lane == 0)
            out[(size_t)b * O_DIM + o0 + r] = s * red;
    }
}

extern "C" void kernel_launch(void* const* d_in, const int* in_sizes, int n_in,
                              void* d_out, int out_size)
{
    (void)in_sizes; (void)n_in; (void)out_size;
    const float* x      = (const float*)d_in[0];
    const int4*  et4    = (const int4*)d_in[1];
    const int*   op_idx = (const int*)d_in[2];
    float*       out    = (float*)d_out;

    const int blocks = B_DIM * GROUPS_PER_B;   // 64 * 64 = 4096
    ffcl_kernel<<<blocks, THREADS>>>(x, et4, op_idx, out);
}